// round 14
// baseline (speedup 1.0000x reference)
#include <cuda_runtime.h>

// Problem constants (derived exactly from the reference's linspace/band math)
#define NB      32            // 8*4 flattened batches
#define CC      2             // channels summed into mag
#define FNUM    2999          // band freqs (30010..59990 step 10)
#define TNUM    400
#define FCIDX   1199          // band index of 42000 Hz
#define NNOISE  2598          // freqs: idx<999 (f<40k) or idx>=1400 (f>44k)
#define CH      64            // NB*CC leading channels of flattened x
#define FT      (FNUM*TNUM)   // 1,199,600
#define NSTRIDE (CC*FT)       // per-batch stride (2,399,200)
#define TOTAL   (CH*FT)       // 76,774,400 elements
#define TQ      (TNUM/4)      // 100 float4 per f-row

// float4-quanta geometry of the noise region (two contiguous chunks)
#define QA      99900         // chunk A: f in [0,999)     -> 999*100 quanta
#define QB      159900        // chunk B: f in [1400,2999) -> 1599*100 quanta
#define QC      (QA+QB)       // per (batch,channel): 259,800
#define QPB     (2*QC)        // per batch (both channels): 519,600
#define FT4     (FT/4)        // 299,900 quanta per channel
#define BSTART  140000        // chunk B start offset in quanta (1400*100)

#define NOISEBX 64            // noise blocks per batch
#define ZBLOCKS 2048          // zero-fill blocks

__device__ float d_partial[NB * NOISEBX];
__device__ int   d_mid[NB];
__device__ int   d_hb[NB];

// ---------------------------------------------------------------------------
// K_noise: PURE-READ. Per-batch noise sum; unroll 8 + dual accumulators.
//          (At ceiling: 42.9us, 6.28 TB/s — unchanged.)
// ---------------------------------------------------------------------------
__global__ __launch_bounds__(256) void k_noise(const float* __restrict__ x) {
    int n = blockIdx.y;
    const float4* base = reinterpret_cast<const float4*>(x)
                       + (long long)n * (NSTRIDE / 4);
    float acc0 = 0.f, acc1 = 0.f;
    #pragma unroll 8
    for (int r = blockIdx.x * 256 + threadIdx.x; r < QPB; r += NOISEBX * 256) {
        int c  = (r >= QC) ? 1 : 0;
        int r2 = r - c * QC;
        int off = c * FT4 + ((r2 < QA) ? r2 : (r2 + (BSTART - QA)));
        float4 v = __ldcs(base + off);
        acc0 += fabsf(v.x) + fabsf(v.y);
        acc1 += fabsf(v.z) + fabsf(v.w);
    }
    __shared__ float sh[256];
    sh[threadIdx.x] = acc0 + acc1;
    __syncthreads();
    for (int st = 128; st > 0; st >>= 1) {
        if (threadIdx.x < st) sh[threadIdx.x] += sh[threadIdx.x + st];
        __syncthreads();
    }
    if (threadIdx.x == 0) d_partial[n * NOISEBX + blockIdx.x] = sh[0];
}

// ---------------------------------------------------------------------------
// K_stats: per-batch. Parallel argmax (first-index-wins), signal window,
//          noise mean finalize, snr -> hb.
// ---------------------------------------------------------------------------
__global__ __launch_bounds__(256) void k_stats(const float* __restrict__ x) {
    int n = blockIdx.x;
    __shared__ float mag[TNUM];
    __shared__ float bv[256];
    __shared__ int   bi[256];
    const float* p0 = x + (long long)n * NSTRIDE + (long long)FCIDX * TNUM;
    const float* p1 = p0 + FT;
    for (int t = threadIdx.x; t < TNUM; t += 256)
        mag[t] = fabsf(p0[t]) + fabsf(p1[t]);
    __syncthreads();
    float best = -1.f; int bidx = TNUM;
    for (int t = threadIdx.x; t < TNUM; t += 256)
        if (mag[t] > best) { best = mag[t]; bidx = t; }
    bv[threadIdx.x] = best; bi[threadIdx.x] = bidx;
    __syncthreads();
    for (int st = 128; st > 0; st >>= 1) {
        if (threadIdx.x < st) {
            float ov = bv[threadIdx.x + st]; int oi = bi[threadIdx.x + st];
            if (ov > bv[threadIdx.x] ||
                (ov == bv[threadIdx.x] && oi < bi[threadIdx.x])) {
                bv[threadIdx.x] = ov; bi[threadIdx.x] = oi;
            }
        }
        __syncthreads();
    }
    if (threadIdx.x == 0) {
        int mid = bi[0];
        float sig = 0.f;
        int lo = max(0, mid - 20), hi = min(TNUM, mid + 20);
        for (int t = lo; t < hi; t++) sig += mag[t];
        float noise = 0.f;
        for (int s = 0; s < NOISEBX; s++) noise += d_partial[n * NOISEBX + s];
        noise /= (float)(NNOISE * TNUM);
        float d   = sig - noise;
        float snr = 10.0f * log10f((d * d) / (noise * noise));
        float hbf = truncf(6.0f * (snr - 48.0f) + 27.0f);
        hbf = fminf(hbf, 3000.0f);
        int hb = (hbf >= 8.0f) ? (int)hbf : 8;   // also maps NaN -> 8
        d_mid[n] = mid;
        d_hb[n]  = hb;
    }
}

// ---------------------------------------------------------------------------
// K_zero: PURE-WRITE, branch-free. Streaming zero-fill of the whole output
//         (band region included; k_band overwrites it afterwards).
// ---------------------------------------------------------------------------
__global__ __launch_bounds__(256) void k_zero(float* __restrict__ out) {
    const int nvec = TOTAL / 4;  // 19,193,600 float4 stores
    float4 z = make_float4(0.f, 0.f, 0.f, 0.f);
    float4* o4 = reinterpret_cast<float4*>(out);
    #pragma unroll 8
    for (int i = blockIdx.x * 256 + threadIdx.x; i < nvec; i += ZBLOCKS * 256)
        __stcs(&o4[i], z);
}

// ---------------------------------------------------------------------------
// K_band: tiny. Overwrites the contiguous union span [qlo, qhi) per channel
//         with the keep-selected values (x where kept by any batch, else 0).
//         One block per channel; ~1600 quanta each. Runs after k_zero, so
//         ordering guarantees the final value everywhere is correct.
// ---------------------------------------------------------------------------
__global__ __launch_bounds__(256) void k_band(const float* __restrict__ x,
                                              float* __restrict__ out) {
    __shared__ int s_mid[NB], s_hb[NB], s_q[2];
    if (threadIdx.x < NB) {
        s_mid[threadIdx.x] = d_mid[threadIdx.x];
        s_hb[threadIdx.x]  = d_hb[threadIdx.x];
    }
    if (threadIdx.x == 0) {
        int mh = 8;
        #pragma unroll
        for (int n = 0; n < NB; n++) mh = max(mh, d_hb[n]);
        int fmin = max(0, FCIDX - mh), fmax = min(FNUM, FCIDX + mh);
        s_q[0] = fmin * TQ;  // qlo
        s_q[1] = fmax * TQ;  // qhi
    }
    __syncthreads();
    int qlo = s_q[0], qhi = s_q[1];

    int ch = blockIdx.x;
    const float4* xi = reinterpret_cast<const float4*>(x) + (long long)ch * FT4;
    float4*       oo = reinterpret_cast<float4*>(out)     + (long long)ch * FT4;

    for (int i = qlo + threadIdx.x; i < qhi; i += 256) {
        int f  = i / TQ;
        int t0 = (i - f * TQ) * 4;         // first of 4 t's in this quantum
        bool k0 = false, k1 = false, k2 = false, k3 = false;
        #pragma unroll
        for (int n = 0; n < NB; n++) {
            int hb = s_hb[n];
            if (f >= FCIDX - hb && f < FCIDX + hb) {
                int tlo = s_mid[n] - 8, thi = s_mid[n] + 8;
                k0 |= (t0     >= tlo) & (t0     < thi);
                k1 |= (t0 + 1 >= tlo) & (t0 + 1 < thi);
                k2 |= (t0 + 2 >= tlo) & (t0 + 2 < thi);
                k3 |= (t0 + 3 >= tlo) & (t0 + 3 < thi);
            }
        }
        float4 v = xi[i];
        float4 r;
        r.x = k0 ? v.x : 0.f;
        r.y = k1 ? v.y : 0.f;
        r.z = k2 ? v.z : 0.f;
        r.w = k3 ? v.w : 0.f;
        oo[i] = r;
    }
}

extern "C" void kernel_launch(void* const* d_in, const int* in_sizes, int n_in,
                              void* d_out, int out_size) {
    const float* x = (const float*)d_in[0];
    float* out = (float*)d_out;
    (void)in_sizes; (void)n_in; (void)out_size;

    k_noise<<<dim3(NOISEBX, NB), 256>>>(x);   // pure read  (266 MB)
    k_stats<<<NB, 256>>>(x);                  // tiny
    k_zero <<<ZBLOCKS, 256>>>(out);           // pure write (307 MB), branch-free
    k_band <<<CH, 256>>>(x, out);             // tiny band overwrite (~1.6 MB)
}

// round 15
// speedup vs baseline: 1.0599x; 1.0599x over previous
#include <cuda_runtime.h>

// Problem constants (derived exactly from the reference's linspace/band math)
#define NB      32            // 8*4 flattened batches
#define CC      2             // channels summed into mag
#define FNUM    2999          // band freqs (30010..59990 step 10)
#define TNUM    400
#define FCIDX   1199          // band index of 42000 Hz
#define NNOISE  2598          // freqs: idx<999 (f<40k) or idx>=1400 (f>44k)
#define CH      64            // NB*CC leading channels of flattened x
#define FT      (FNUM*TNUM)   // 1,199,600
#define NSTRIDE (CC*FT)       // per-batch stride (2,399,200)
#define TOTAL   (CH*FT)       // 76,774,400 elements
#define TQ      (TNUM/4)      // 100 float4 per f-row

// float4-quanta geometry of the noise region (two contiguous chunks)
#define QA      99900         // chunk A: f in [0,999)     -> 999*100 quanta
#define QB      159900        // chunk B: f in [1400,2999) -> 1599*100 quanta
#define QC      (QA+QB)       // per (batch,channel): 259,800
#define QPB     (2*QC)        // per batch (both channels): 519,600
#define FT4     (FT/4)        // 299,900 quanta per channel
#define BSTART  140000        // chunk B start offset in quanta (1400*100)

#define NOISEBX 64            // noise blocks per batch
#define ZBLOCKS 2048          // zero-fill blocks
#define BANDBX  8             // x-blocks per channel for k_band (512 total)

__device__ float d_partial[NB * NOISEBX];
__device__ int   d_mid[NB];
__device__ int   d_hb[NB];

// ---------------------------------------------------------------------------
// K_noise: PURE-READ. Per-batch noise sum; unroll 8 + dual accumulators.
//          (Measured 42.9us @ 6.28 TB/s — at ceiling, unchanged.)
// ---------------------------------------------------------------------------
__global__ __launch_bounds__(256) void k_noise(const float* __restrict__ x) {
    int n = blockIdx.y;
    const float4* base = reinterpret_cast<const float4*>(x)
                       + (long long)n * (NSTRIDE / 4);
    float acc0 = 0.f, acc1 = 0.f;
    #pragma unroll 8
    for (int r = blockIdx.x * 256 + threadIdx.x; r < QPB; r += NOISEBX * 256) {
        int c  = (r >= QC) ? 1 : 0;
        int r2 = r - c * QC;
        int off = c * FT4 + ((r2 < QA) ? r2 : (r2 + (BSTART - QA)));
        float4 v = __ldcs(base + off);
        acc0 += fabsf(v.x) + fabsf(v.y);
        acc1 += fabsf(v.z) + fabsf(v.w);
    }
    __shared__ float sh[256];
    sh[threadIdx.x] = acc0 + acc1;
    __syncthreads();
    for (int st = 128; st > 0; st >>= 1) {
        if (threadIdx.x < st) sh[threadIdx.x] += sh[threadIdx.x + st];
        __syncthreads();
    }
    if (threadIdx.x == 0) d_partial[n * NOISEBX + blockIdx.x] = sh[0];
}

// ---------------------------------------------------------------------------
// K_stats: per-batch. Parallel argmax (first-index-wins), signal window,
//          noise mean finalize, snr -> hb.
// ---------------------------------------------------------------------------
__global__ __launch_bounds__(256) void k_stats(const float* __restrict__ x) {
    int n = blockIdx.x;
    __shared__ float mag[TNUM];
    __shared__ float bv[256];
    __shared__ int   bi[256];
    const float* p0 = x + (long long)n * NSTRIDE + (long long)FCIDX * TNUM;
    const float* p1 = p0 + FT;
    for (int t = threadIdx.x; t < TNUM; t += 256)
        mag[t] = fabsf(p0[t]) + fabsf(p1[t]);
    __syncthreads();
    float best = -1.f; int bidx = TNUM;
    for (int t = threadIdx.x; t < TNUM; t += 256)
        if (mag[t] > best) { best = mag[t]; bidx = t; }
    bv[threadIdx.x] = best; bi[threadIdx.x] = bidx;
    __syncthreads();
    for (int st = 128; st > 0; st >>= 1) {
        if (threadIdx.x < st) {
            float ov = bv[threadIdx.x + st]; int oi = bi[threadIdx.x + st];
            if (ov > bv[threadIdx.x] ||
                (ov == bv[threadIdx.x] && oi < bi[threadIdx.x])) {
                bv[threadIdx.x] = ov; bi[threadIdx.x] = oi;
            }
        }
        __syncthreads();
    }
    if (threadIdx.x == 0) {
        int mid = bi[0];
        float sig = 0.f;
        int lo = max(0, mid - 20), hi = min(TNUM, mid + 20);
        for (int t = lo; t < hi; t++) sig += mag[t];
        float noise = 0.f;
        for (int s = 0; s < NOISEBX; s++) noise += d_partial[n * NOISEBX + s];
        noise /= (float)(NNOISE * TNUM);
        float d   = sig - noise;
        float snr = 10.0f * log10f((d * d) / (noise * noise));
        float hbf = truncf(6.0f * (snr - 48.0f) + 27.0f);
        hbf = fminf(hbf, 3000.0f);
        int hb = (hbf >= 8.0f) ? (int)hbf : 8;   // also maps NaN -> 8
        d_mid[n] = mid;
        d_hb[n]  = hb;
    }
}

// ---------------------------------------------------------------------------
// K_zero: PURE-WRITE, branch-free. (Measured ~48.5us implied — unchanged.)
// ---------------------------------------------------------------------------
__global__ __launch_bounds__(256) void k_zero(float* __restrict__ out) {
    const int nvec = TOTAL / 4;  // 19,193,600 float4 stores
    float4 z = make_float4(0.f, 0.f, 0.f, 0.f);
    float4* o4 = reinterpret_cast<float4*>(out);
    #pragma unroll 8
    for (int i = blockIdx.x * 256 + threadIdx.x; i < nvec; i += ZBLOCKS * 256)
        __stcs(&o4[i], z);
}

// ---------------------------------------------------------------------------
// K_band: overwrites the contiguous union span [qlo, qhi) per channel with
//   keep-selected values. R14 fix: 512 blocks (8 per channel) instead of 64,
//   NB loop NOT unrolled + single bitmask accumulator -> low registers,
//   normal occupancy. ~1 quantum per thread typical.
// ---------------------------------------------------------------------------
__global__ __launch_bounds__(256) void k_band(const float* __restrict__ x,
                                              float* __restrict__ out) {
    __shared__ int s_mid[NB], s_hb[NB], s_q[2];
    if (threadIdx.x < NB) {
        s_mid[threadIdx.x] = d_mid[threadIdx.x];
        s_hb[threadIdx.x]  = d_hb[threadIdx.x];
    }
    if (threadIdx.x == 0) {
        int mh = 8;
        for (int n = 0; n < NB; n++) mh = max(mh, d_hb[n]);
        int fmin = max(0, FCIDX - mh), fmax = min(FNUM, FCIDX + mh);
        s_q[0] = fmin * TQ;  // qlo
        s_q[1] = fmax * TQ;  // qhi
    }
    __syncthreads();
    int qlo = s_q[0], qhi = s_q[1];

    int ch = blockIdx.y;
    const float4* xi = reinterpret_cast<const float4*>(x) + (long long)ch * FT4;
    float4*       oo = reinterpret_cast<float4*>(out)     + (long long)ch * FT4;

    for (int i = qlo + blockIdx.x * 256 + threadIdx.x; i < qhi;
         i += BANDBX * 256) {
        int f  = i / TQ;
        int t0 = (i - f * TQ) * 4;         // first of 4 t's in this quantum
        unsigned km = 0;                    // bit b set => t0+b kept
        #pragma unroll 1
        for (int n = 0; n < NB; n++) {
            int hb = s_hb[n];
            if (f >= FCIDX - hb && f < FCIDX + hb) {
                int rlo = s_mid[n] - 8 - t0;   // kept lanes: [rlo, rhi)
                int rhi = s_mid[n] + 8 - t0;
                rlo = max(rlo, 0); rhi = min(rhi, 4);
                if (rlo < rhi)
                    km |= ((1u << (rhi - rlo)) - 1u) << rlo;
            }
        }
        float4 v = xi[i];
        float4 r;
        r.x = (km & 1u) ? v.x : 0.f;
        r.y = (km & 2u) ? v.y : 0.f;
        r.z = (km & 4u) ? v.z : 0.f;
        r.w = (km & 8u) ? v.w : 0.f;
        oo[i] = r;
    }
}

extern "C" void kernel_launch(void* const* d_in, const int* in_sizes, int n_in,
                              void* d_out, int out_size) {
    const float* x = (const float*)d_in[0];
    float* out = (float*)d_out;
    (void)in_sizes; (void)n_in; (void)out_size;

    k_noise<<<dim3(NOISEBX, NB), 256>>>(x);   // pure read  (266 MB)
    k_stats<<<NB, 256>>>(x);                  // tiny
    k_zero <<<ZBLOCKS, 256>>>(out);           // pure write (307 MB), branch-free
    k_band <<<dim3(BANDBX, CH), 256>>>(x, out); // band overwrite (~1.6 MB)
}

// round 17
// speedup vs baseline: 1.1164x; 1.0533x over previous
#include <cuda_runtime.h>

// Problem constants (derived exactly from the reference's linspace/band math)
#define NB      32            // 8*4 flattened batches
#define CC      2             // channels summed into mag
#define FNUM    2999          // band freqs (30010..59990 step 10)
#define TNUM    400
#define FCIDX   1199          // band index of 42000 Hz
#define NNOISE  2598          // freqs: idx<999 (f<40k) or idx>=1400 (f>44k)
#define CH      64            // NB*CC leading channels of flattened x
#define FT      (FNUM*TNUM)   // 1,199,600
#define NSTRIDE (CC*FT)       // per-batch stride (2,399,200)
#define TOTAL   (CH*FT)       // 76,774,400 elements
#define TQ      (TNUM/4)      // 100 float4 per f-row

// float4-quanta geometry of the noise region (two contiguous chunks)
#define QA      99900         // chunk A: f in [0,999)     -> 999*100 quanta
#define QB      159900        // chunk B: f in [1400,2999) -> 1599*100 quanta
#define QC      (QA+QB)       // per (batch,channel): 259,800
#define QPB     (2*QC)        // per batch (both channels): 519,600
#define FT4     (FT/4)        // 299,900 quanta per channel
#define BSTART  140000        // chunk B start offset in quanta (1400*100)

#define NOISEBX 64            // noise blocks per batch
#define ZXBLK   32            // zero blocks per channel
#define BANDBX  8             // band blocks per channel

__device__ float d_partial[NB * NOISEBX];
__device__ int   d_mid[NB];
__device__ int   d_hb[NB];

// ---------------------------------------------------------------------------
// K_noise: PURE-READ. Per-batch noise sum; unroll 8 + dual accumulators.
//          (Measured 42.9us @ 6.28 TB/s — at ceiling, unchanged.)
// ---------------------------------------------------------------------------
__global__ __launch_bounds__(256) void k_noise(const float* __restrict__ x) {
    int n = blockIdx.y;
    const float4* base = reinterpret_cast<const float4*>(x)
                       + (long long)n * (NSTRIDE / 4);
    float acc0 = 0.f, acc1 = 0.f;
    #pragma unroll 8
    for (int r = blockIdx.x * 256 + threadIdx.x; r < QPB; r += NOISEBX * 256) {
        int c  = (r >= QC) ? 1 : 0;
        int r2 = r - c * QC;
        int off = c * FT4 + ((r2 < QA) ? r2 : (r2 + (BSTART - QA)));
        float4 v = __ldcs(base + off);
        acc0 += fabsf(v.x) + fabsf(v.y);
        acc1 += fabsf(v.z) + fabsf(v.w);
    }
    __shared__ float sh[256];
    sh[threadIdx.x] = acc0 + acc1;
    __syncthreads();
    for (int st = 128; st > 0; st >>= 1) {
        if (threadIdx.x < st) sh[threadIdx.x] += sh[threadIdx.x + st];
        __syncthreads();
    }
    if (threadIdx.x == 0) d_partial[n * NOISEBX + blockIdx.x] = sh[0];
}

// ---------------------------------------------------------------------------
// K_stats: per-batch. Parallel argmax (first-index-wins), signal window,
//          noise mean finalize, snr -> hb.
// ---------------------------------------------------------------------------
__global__ __launch_bounds__(256) void k_stats(const float* __restrict__ x) {
    int n = blockIdx.x;
    __shared__ float mag[TNUM];
    __shared__ float bv[256];
    __shared__ int   bi[256];
    const float* p0 = x + (long long)n * NSTRIDE + (long long)FCIDX * TNUM;
    const float* p1 = p0 + FT;
    for (int t = threadIdx.x; t < TNUM; t += 256)
        mag[t] = fabsf(p0[t]) + fabsf(p1[t]);
    __syncthreads();
    float best = -1.f; int bidx = TNUM;
    for (int t = threadIdx.x; t < TNUM; t += 256)
        if (mag[t] > best) { best = mag[t]; bidx = t; }
    bv[threadIdx.x] = best; bi[threadIdx.x] = bidx;
    __syncthreads();
    for (int st = 128; st > 0; st >>= 1) {
        if (threadIdx.x < st) {
            float ov = bv[threadIdx.x + st]; int oi = bi[threadIdx.x + st];
            if (ov > bv[threadIdx.x] ||
                (ov == bv[threadIdx.x] && oi < bi[threadIdx.x])) {
                bv[threadIdx.x] = ov; bi[threadIdx.x] = oi;
            }
        }
        __syncthreads();
    }
    if (threadIdx.x == 0) {
        int mid = bi[0];
        float sig = 0.f;
        int lo = max(0, mid - 20), hi = min(TNUM, mid + 20);
        for (int t = lo; t < hi; t++) sig += mag[t];
        float noise = 0.f;
        for (int s = 0; s < NOISEBX; s++) noise += d_partial[n * NOISEBX + s];
        noise /= (float)(NNOISE * TNUM);
        float d   = sig - noise;
        float snr = 10.0f * log10f((d * d) / (noise * noise));
        float hbf = truncf(6.0f * (snr - 48.0f) + 27.0f);
        hbf = fminf(hbf, 3000.0f);
        int hb = (hbf >= 8.0f) ? (int)hbf : 8;   // also maps NaN -> 8
        d_mid[n] = mid;
        d_hb[n]  = hb;
    }
}

// ---------------------------------------------------------------------------
// K_zero_band: heterogeneous grid (ZXBLK+BANDBX, CH).
//   x <  ZXBLK : zero-fill this channel OUTSIDE [qlo,qhi) — minimal
//                predicated streaming store, nothing else in the loop.
//   x >= ZXBLK : keep-select overwrite of the band span [qlo,qhi).
//   Regions are disjoint -> no write race; the band blocks' latency work
//   hides under the zero blocks' ~49us store wave. One launch.
// ---------------------------------------------------------------------------
__global__ __launch_bounds__(256) void k_zero_band(const float* __restrict__ x,
                                                   float* __restrict__ out) {
    __shared__ int s_mid[NB], s_hb[NB], s_q[2];
    if (threadIdx.x < NB) {
        s_mid[threadIdx.x] = d_mid[threadIdx.x];
        s_hb[threadIdx.x]  = d_hb[threadIdx.x];
    }
    if (threadIdx.x == 0) {
        int mh = 8;
        for (int n = 0; n < NB; n++) mh = max(mh, d_hb[n]);
        int fmin = max(0, FCIDX - mh), fmax = min(FNUM, FCIDX + mh);
        s_q[0] = fmin * TQ;  // qlo
        s_q[1] = fmax * TQ;  // qhi
    }
    __syncthreads();
    int qlo = s_q[0], qhi = s_q[1];

    int ch = blockIdx.y;
    const float4* xi = reinterpret_cast<const float4*>(x) + (long long)ch * FT4;
    float4*       oo = reinterpret_cast<float4*>(out)     + (long long)ch * FT4;

    if (blockIdx.x < ZXBLK) {
        // ---- zero duty: predicated streaming store, no other work ----
        float4 z = make_float4(0.f, 0.f, 0.f, 0.f);
        #pragma unroll 8
        for (int i = blockIdx.x * 256 + threadIdx.x; i < FT4; i += ZXBLK * 256)
            if (i < qlo || i >= qhi)
                __stcs(&oo[i], z);
    } else {
        // ---- band duty: keep-select overwrite of [qlo, qhi) ----
        int bx = blockIdx.x - ZXBLK;
        for (int i = qlo + bx * 256 + threadIdx.x; i < qhi; i += BANDBX * 256) {
            int f  = i / TQ;
            int t0 = (i - f * TQ) * 4;     // first of 4 t's in this quantum
            unsigned km = 0;                // bit b set => t0+b kept
            #pragma unroll 1
            for (int n = 0; n < NB; n++) {
                int hb = s_hb[n];
                if (f >= FCIDX - hb && f < FCIDX + hb) {
                    int rlo = s_mid[n] - 8 - t0;   // kept lanes: [rlo, rhi)
                    int rhi = s_mid[n] + 8 - t0;
                    rlo = max(rlo, 0); rhi = min(rhi, 4);
                    if (rlo < rhi)
                        km |= ((1u << (rhi - rlo)) - 1u) << rlo;
                }
            }
            float4 v = xi[i];
            float4 r;
            r.x = (km & 1u) ? v.x : 0.f;
            r.y = (km & 2u) ? v.y : 0.f;
            r.z = (km & 4u) ? v.z : 0.f;
            r.w = (km & 8u) ? v.w : 0.f;
            oo[i] = r;
        }
    }
}

extern "C" void kernel_launch(void* const* d_in, const int* in_sizes, int n_in,
                              void* d_out, int out_size) {
    const float* x = (const float*)d_in[0];
    float* out = (float*)d_out;
    (void)in_sizes; (void)n_in; (void)out_size;

    k_noise    <<<dim3(NOISEBX, NB), 256>>>(x);          // pure read (266 MB)
    k_stats    <<<NB, 256>>>(x);                         // tiny
    k_zero_band<<<dim3(ZXBLK + BANDBX, CH), 256>>>(x, out); // write + band, 1 launch
}